// round 9
// baseline (speedup 1.0000x reference)
#include <cuda_runtime.h>
#include <cuda_bf16.h>
#include <cstdint>

#define NUM_CLASSES 1000
#define CPAD        1024                   // padded class count
#define FEAT_DIM    256
#define N_ROWS      262144
#define ALPHA       0.5f
#define HB          64                     // index blocks (all co-resident)
#define ROWS_PER_HB (N_ROWS / HB)          // 4096
#define RPT         (ROWS_PER_HB / 256)    // 16 rows per thread
#define MAXTILE     2048                   // rows staged per class tile

// Scratch (device globals — no allocation allowed).
__device__ int g_parthist[HB * CPAD];
__device__ int g_offsets[NUM_CLASSES];
__device__ int g_counts[NUM_CLASSES];
__device__ int g_rowidx[N_ROWS];
__device__ unsigned g_bar_cnt = 0;
__device__ unsigned g_bar_gen = 0;
__device__ int g_work = 0;

// Grid-wide barrier: single use per launch; counter self-resets, generation
// bump releases waiters. All HB blocks are co-resident (64 << 148 SMs).
__device__ __forceinline__ void grid_barrier() {
    __syncthreads();
    if (threadIdx.x == 0) {
        __threadfence();
        unsigned gen = atomicAdd(&g_bar_gen, 0u);
        unsigned old = atomicAdd(&g_bar_cnt, 1u);
        if (old == HB - 1) {
            atomicExch(&g_bar_cnt, 0u);
            __threadfence();
            atomicAdd(&g_bar_gen, 1u);
        } else {
            while (atomicAdd(&g_bar_gen, 0u) == gen) { }
        }
        __threadfence();
    }
    __syncthreads();
}

// ---------------------------------------------------------------------------
// K1: fused index build — smem hist+rank (regs), barrier, redundant scan,
// direct place. Also resets the work-steal counter for K2.
// ---------------------------------------------------------------------------
__global__ void __launch_bounds__(256)
index_kernel(const int* __restrict__ labels) {
    __shared__ int shA[CPAD];   // phase A: histogram; phase B: totals -> bases
    __shared__ int shP[CPAD];   // phase B: this block's prefix over earlier blocks
    __shared__ int shS[256];    // phase B: block scan of thread sums

    int tid = threadIdx.x;
    int myB = blockIdx.x;

    if (myB == 0 && tid == 0) g_work = 0;   // reset work-steal counter

    // --- Phase A: histogram + ranks (held in registers) ---
#pragma unroll
    for (int c = tid; c < CPAD; c += 256) shA[c] = 0;
    __syncthreads();

    const int4* __restrict__ lab4 = reinterpret_cast<const int4*>(labels);
    int base4 = myB * (ROWS_PER_HB / 4);

    int lab[RPT], rnk[RPT];
#pragma unroll
    for (int k = 0; k < RPT / 4; k++) {
        int4 L = lab4[base4 + tid + k * 256];
        lab[k * 4 + 0] = L.x; lab[k * 4 + 1] = L.y;
        lab[k * 4 + 2] = L.z; lab[k * 4 + 3] = L.w;
    }
#pragma unroll
    for (int e = 0; e < RPT; e++) rnk[e] = atomicAdd(&shA[lab[e]], 1);
    __syncthreads();

#pragma unroll
    for (int c = tid; c < CPAD; c += 256)
        g_parthist[myB * CPAD + c] = shA[c];

    // --- Grid barrier: all partial histograms visible ---
    grid_barrier();

    // --- Phase B: totals + own-prefix in one sweep (L2-hot, coalesced) ---
#pragma unroll 1
    for (int q = 0; q < 4; q++) {
        int c = tid + q * 256;
        int tot = 0, pre = 0;
#pragma unroll 8
        for (int b = 0; b < HB; b++) {
            int v = g_parthist[b * CPAD + c];
            tot += v;
            pre += (b < myB) ? v : 0;
        }
        shA[c] = tot;
        shP[c] = pre;
    }
    __syncthreads();

    // Block-wide exclusive scan over 1024 class totals (4 contiguous/thread).
    int t4 = tid * 4;
    int s0 = shA[t4], s1 = shA[t4 + 1], s2 = shA[t4 + 2], s3 = shA[t4 + 3];
    int mysum = s0 + s1 + s2 + s3;
    shS[tid] = mysum;
    __syncthreads();
#pragma unroll
    for (int off = 1; off < 256; off <<= 1) {
        int v = (tid >= off) ? shS[tid - off] : 0;
        __syncthreads();
        shS[tid] += v;
        __syncthreads();
    }
    int e0 = shS[tid] - mysum;          // exclusive offset of class t4
    int e1 = e0 + s0, e2 = e1 + s1, e3 = e2 + s2;

    if (myB == 0) {                     // publish for sum_ema
        if (t4 + 0 < NUM_CLASSES) { g_offsets[t4 + 0] = e0; g_counts[t4 + 0] = s0; }
        if (t4 + 1 < NUM_CLASSES) { g_offsets[t4 + 1] = e1; g_counts[t4 + 1] = s1; }
        if (t4 + 2 < NUM_CLASSES) { g_offsets[t4 + 2] = e2; g_counts[t4 + 2] = s2; }
        if (t4 + 3 < NUM_CLASSES) { g_offsets[t4 + 3] = e3; g_counts[t4 + 3] = s3; }
    }

    // This block's scatter base per class (overwrite shA — own-thread slots).
    shA[t4 + 0] = e0 + shP[t4 + 0];
    shA[t4 + 1] = e1 + shP[t4 + 1];
    shA[t4 + 2] = e2 + shP[t4 + 2];
    shA[t4 + 3] = e3 + shP[t4 + 3];
    __syncthreads();

    // --- Place: register-held rows straight to class-sorted order ---
    int rowbase = myB * ROWS_PER_HB;
#pragma unroll
    for (int k = 0; k < RPT / 4; k++) {
#pragma unroll
        for (int e = 0; e < 4; e++) {
            int idx = k * 4 + e;
            int row = rowbase + (tid + k * 256) * 4 + e;
            g_rowidx[shA[lab[idx]] + rnk[idx]] = row;
        }
    }
}

// ---------------------------------------------------------------------------
// K2: persistent work-stealing gather-sum + fused mean/EMA.
// Indices staged in smem so the inner loop's feature LDGs are independent.
// 256 threads: tid -> (row slot r4 0..3, float4 column c4 0..63).
// ---------------------------------------------------------------------------
#define F4ADD(a, b) { (a).x += (b).x; (a).y += (b).y; (a).z += (b).z; (a).w += (b).w; }

__global__ void __launch_bounds__(256, 5)
sum_ema_kernel(const float* __restrict__ features,
               const float* __restrict__ centers,
               float* __restrict__ out) {
    __shared__ int sidx[MAXTILE];
    __shared__ float4 sred[256];
    __shared__ int s_w;

    int tid = threadIdx.x;
    int r4 = tid >> 6;   // row slot 0..3
    int c4 = tid & 63;   // float4 column 0..63
    const float4* __restrict__ f4 = reinterpret_cast<const float4*>(features);

    while (true) {
        if (tid == 0) s_w = atomicAdd(&g_work, 1);
        __syncthreads();
        int cls = s_w;
        if (cls >= NUM_CLASSES) break;

        int n = g_counts[cls];
        int off = g_offsets[cls];

        float4 a0 = make_float4(0.f, 0.f, 0.f, 0.f);
        float4 a1 = a0, a2 = a0, a3 = a0;

        for (int t0 = 0; t0 < n; t0 += MAXTILE) {
            int tn = min(n - t0, MAXTILE);
            for (int j = tid; j < tn; j += 256) sidx[j] = g_rowidx[off + t0 + j];
            __syncthreads();

            int i = r4;
            for (; i + 12 < tn; i += 16) {
                int i0 = sidx[i];
                int i1 = sidx[i + 4];
                int i2 = sidx[i + 8];
                int i3 = sidx[i + 12];
                float4 v0 = __ldcs(&f4[(size_t)i0 * 64 + c4]);
                float4 v1 = __ldcs(&f4[(size_t)i1 * 64 + c4]);
                float4 v2 = __ldcs(&f4[(size_t)i2 * 64 + c4]);
                float4 v3 = __ldcs(&f4[(size_t)i3 * 64 + c4]);
                F4ADD(a0, v0); F4ADD(a1, v1); F4ADD(a2, v2); F4ADD(a3, v3);
            }
            for (; i < tn; i += 4) {
                float4 v = __ldcs(&f4[(size_t)sidx[i] * 64 + c4]);
                F4ADD(a0, v);
            }
            __syncthreads();   // before next tile overwrites sidx
        }
        F4ADD(a0, a1); F4ADD(a2, a3); F4ADD(a0, a2);

        sred[tid] = a0;
        __syncthreads();

        if (tid < 64) {
            float4 t0 = sred[tid];
            float4 t1 = sred[tid + 64];
            float4 t2 = sred[tid + 128];
            float4 t3 = sred[tid + 192];
            F4ADD(t0, t1); F4ADD(t2, t3); F4ADD(t0, t2);

            float4 c = reinterpret_cast<const float4*>(centers)[(size_t)cls * 64 + tid];
            float4 o;
            if (n > 0) {
                float scale = ALPHA / (float)n;   // ALPHA * mean
                o.x = (1.0f - ALPHA) * c.x + scale * t0.x;
                o.y = (1.0f - ALPHA) * c.y + scale * t0.y;
                o.z = (1.0f - ALPHA) * c.z + scale * t0.z;
                o.w = (1.0f - ALPHA) * c.w + scale * t0.w;
            } else {
                o = c;
            }
            reinterpret_cast<float4*>(out)[(size_t)cls * 64 + tid] = o;
        }
        __syncthreads();   // protect s_w / sred / sidx for next class
    }
}

// ---------------------------------------------------------------------------
// Launch: features f32 [N,256], labels i32 [N], centers f32 [1000,256].
// ---------------------------------------------------------------------------
extern "C" void kernel_launch(void* const* d_in, const int* in_sizes, int n_in,
                              void* d_out, int out_size) {
    const float* features = (const float*)d_in[0];
    const int* labels     = (const int*)d_in[1];
    const float* centers  = (const float*)d_in[2];
    float* out            = (float*)d_out;

    index_kernel<<<HB, 256>>>(labels);
    sum_ema_kernel<<<740, 256>>>(features, centers, out);
}

// round 11
// speedup vs baseline: 1.0213x; 1.0213x over previous
#include <cuda_runtime.h>
#include <cuda_bf16.h>
#include <cstdint>

#define NUM_CLASSES 1000
#define CPAD        1024                   // padded class count
#define FEAT_DIM    256
#define N_ROWS      262144
#define ALPHA       0.5f
#define HB          64                     // index blocks
#define NB          512                    // total blocks (all co-resident @4/SM)
#define ROWS_PER_HB (N_ROWS / HB)          // 4096
#define RPT         (ROWS_PER_HB / 256)    // 16 rows per thread

// Scratch (device globals — no allocation allowed).
__device__ int g_parthist[HB * CPAD];
__device__ int g_offsets[NUM_CLASSES];
__device__ int g_counts[NUM_CLASSES];
__device__ int g_rowidx[N_ROWS];
__device__ unsigned g_cnt1 = 0, g_gen1 = 0;   // barrier among 64 index blocks
__device__ unsigned g_cnt2 = 0, g_gen2 = 0;   // barrier among all 512 blocks

// Spin barrier (sense-reversing via generation counter). Safe: all NB blocks
// are co-resident. Counter self-resets each use -> graph-replay safe.
__device__ __forceinline__ void spin_barrier(unsigned* cnt, unsigned* gen, unsigned nb) {
    __syncthreads();
    if (threadIdx.x == 0) {
        __threadfence();
        unsigned g = atomicAdd(gen, 0u);
        unsigned old = atomicAdd(cnt, 1u);
        if (old == nb - 1) {
            atomicExch(cnt, 0u);
            __threadfence();
            atomicAdd(gen, 1u);
        } else {
            while (atomicAdd(gen, 0u) == g) __nanosleep(64);
        }
        __threadfence();
    }
    __syncthreads();
}

#define F4ADD(a, b) { (a).x += (b).x; (a).y += (b).y; (a).z += (b).z; (a).w += (b).w; }

// ---------------------------------------------------------------------------
// Single persistent kernel: blocks 0..63 build the class-sorted row index
// (smem hist + ranks in regs, barrier, redundant scan, direct place); all
// 512 blocks then gather-sum + fused mean/EMA (R7-measured loop, untouched).
// ---------------------------------------------------------------------------
__global__ void __launch_bounds__(256, 4)
fused_kernel(const int* __restrict__ labels,
             const float* __restrict__ features,
             const float* __restrict__ centers,
             float* __restrict__ out) {
    __shared__ int shA[CPAD];
    __shared__ int shP[CPAD];
    __shared__ int shS[256];
    __shared__ float4 sred[256];

    int tid = threadIdx.x;
    int myB = blockIdx.x;

    if (myB < HB) {
        // =============== INDEX BUILD (blocks 0..63) ===============
        // --- Phase A: histogram + ranks (held in registers) ---
#pragma unroll
        for (int c = tid; c < CPAD; c += 256) shA[c] = 0;
        __syncthreads();

        const int4* __restrict__ lab4 = reinterpret_cast<const int4*>(labels);
        int base4 = myB * (ROWS_PER_HB / 4);

        int lab[RPT], rnk[RPT];
#pragma unroll
        for (int k = 0; k < RPT / 4; k++) {
            int4 L = lab4[base4 + tid + k * 256];
            lab[k * 4 + 0] = L.x; lab[k * 4 + 1] = L.y;
            lab[k * 4 + 2] = L.z; lab[k * 4 + 3] = L.w;
        }
#pragma unroll
        for (int e = 0; e < RPT; e++) rnk[e] = atomicAdd(&shA[lab[e]], 1);
        __syncthreads();

#pragma unroll
        for (int c = tid; c < CPAD; c += 256)
            g_parthist[myB * CPAD + c] = shA[c];

        // --- Barrier #1: partial histograms visible among index blocks ---
        spin_barrier(&g_cnt1, &g_gen1, HB);

        // --- Phase B: totals + own-prefix in one sweep (L2-hot) ---
#pragma unroll 1
        for (int q = 0; q < 4; q++) {
            int c = tid + q * 256;
            int tot = 0, pre = 0;
#pragma unroll 8
            for (int b = 0; b < HB; b++) {
                int v = g_parthist[b * CPAD + c];
                tot += v;
                pre += (b < myB) ? v : 0;
            }
            shA[c] = tot;
            shP[c] = pre;
        }
        __syncthreads();

        // Block-wide exclusive scan over 1024 class totals.
        int t4 = tid * 4;
        int s0 = shA[t4], s1 = shA[t4 + 1], s2 = shA[t4 + 2], s3 = shA[t4 + 3];
        int mysum = s0 + s1 + s2 + s3;
        shS[tid] = mysum;
        __syncthreads();
#pragma unroll
        for (int off = 1; off < 256; off <<= 1) {
            int v = (tid >= off) ? shS[tid - off] : 0;
            __syncthreads();
            shS[tid] += v;
            __syncthreads();
        }
        int e0 = shS[tid] - mysum;
        int e1 = e0 + s0, e2 = e1 + s1, e3 = e2 + s2;

        if (myB == 0) {
            if (t4 + 0 < NUM_CLASSES) { g_offsets[t4 + 0] = e0; g_counts[t4 + 0] = s0; }
            if (t4 + 1 < NUM_CLASSES) { g_offsets[t4 + 1] = e1; g_counts[t4 + 1] = s1; }
            if (t4 + 2 < NUM_CLASSES) { g_offsets[t4 + 2] = e2; g_counts[t4 + 2] = s2; }
            if (t4 + 3 < NUM_CLASSES) { g_offsets[t4 + 3] = e3; g_counts[t4 + 3] = s3; }
        }

        shA[t4 + 0] = e0 + shP[t4 + 0];
        shA[t4 + 1] = e1 + shP[t4 + 1];
        shA[t4 + 2] = e2 + shP[t4 + 2];
        shA[t4 + 3] = e3 + shP[t4 + 3];
        __syncthreads();

        // --- Place: register-held rows straight to class-sorted order ---
        int rowbase = myB * ROWS_PER_HB;
#pragma unroll
        for (int k = 0; k < RPT / 4; k++) {
#pragma unroll
            for (int e = 0; e < 4; e++) {
                int idx = k * 4 + e;
                int row = rowbase + (tid + k * 256) * 4 + e;
                g_rowidx[shA[lab[idx]] + rnk[idx]] = row;
            }
        }
        __threadfence();
    }

    // --- Barrier #2: rowidx/offsets/counts published to all 512 blocks ---
    spin_barrier(&g_cnt2, &g_gen2, NB);

    // =============== GATHER-SUM + EMA (all blocks; R7-measured loop) ========
    int r4 = tid >> 6;   // row slot 0..3
    int c4 = tid & 63;   // float4 column 0..63
    const float4* __restrict__ f4 = reinterpret_cast<const float4*>(features);

#pragma unroll 1
    for (int cls = myB; cls < NUM_CLASSES; cls += NB) {
        int n = g_counts[cls];
        const int* __restrict__ ridx = g_rowidx + g_offsets[cls];

        float4 a0 = make_float4(0.f, 0.f, 0.f, 0.f);
        float4 a1 = a0, a2 = a0, a3 = a0;

        int i = r4;
        for (; i + 12 < n; i += 16) {
            int i0 = ridx[i];
            int i1 = ridx[i + 4];
            int i2 = ridx[i + 8];
            int i3 = ridx[i + 12];
            float4 v0 = __ldcs(&f4[(size_t)i0 * 64 + c4]);
            float4 v1 = __ldcs(&f4[(size_t)i1 * 64 + c4]);
            float4 v2 = __ldcs(&f4[(size_t)i2 * 64 + c4]);
            float4 v3 = __ldcs(&f4[(size_t)i3 * 64 + c4]);
            F4ADD(a0, v0); F4ADD(a1, v1); F4ADD(a2, v2); F4ADD(a3, v3);
        }
        for (; i < n; i += 4) {
            int r = ridx[i];
            float4 v = __ldcs(&f4[(size_t)r * 64 + c4]);
            F4ADD(a0, v);
        }
        F4ADD(a0, a1); F4ADD(a2, a3); F4ADD(a0, a2);

        sred[tid] = a0;
        __syncthreads();

        if (tid < 64) {
            float4 t0 = sred[tid];
            float4 t1 = sred[tid + 64];
            float4 t2 = sred[tid + 128];
            float4 t3 = sred[tid + 192];
            F4ADD(t0, t1); F4ADD(t2, t3); F4ADD(t0, t2);

            float4 c = reinterpret_cast<const float4*>(centers)[(size_t)cls * 64 + tid];
            float4 o;
            if (n > 0) {
                float scale = ALPHA / (float)n;   // ALPHA * mean
                o.x = (1.0f - ALPHA) * c.x + scale * t0.x;
                o.y = (1.0f - ALPHA) * c.y + scale * t0.y;
                o.z = (1.0f - ALPHA) * c.z + scale * t0.z;
                o.w = (1.0f - ALPHA) * c.w + scale * t0.w;
            } else {
                o = c;
            }
            reinterpret_cast<float4*>(out)[(size_t)cls * 64 + tid] = o;
        }
        __syncthreads();   // sred reuse safety for next class
    }
}

// ---------------------------------------------------------------------------
// Launch: features f32 [N,256], labels i32 [N], centers f32 [1000,256].
// ---------------------------------------------------------------------------
extern "C" void kernel_launch(void* const* d_in, const int* in_sizes, int n_in,
                              void* d_out, int out_size) {
    const float* features = (const float*)d_in[0];
    const int* labels     = (const int*)d_in[1];
    const float* centers  = (const float*)d_in[2];
    float* out            = (float*)d_out;

    fused_kernel<<<NB, 256>>>(labels, features, centers, out);
}